// round 1
// baseline (speedup 1.0000x reference)
#include <cuda_runtime.h>
#include <math.h>

// Problem constants
#define BQ   2048
#define TQ   16
#define DQ   2048
#define DHQ  1024
#define NCQ  174
#define DTQ  32768          // D*T
#define RWS  4096           // 2*DH + D  (theta; phi; M rows)
#define CRW  65536          // RWS*T

// ---------------- device scratch (no allocations allowed) ----------------
__device__ float g_inv [DQ];
__device__ float g_cadd[DQ];
__device__ float g_cc  [DQ];
__device__ float g_M   [(size_t)DQ * DQ];        // 16 MB  : W_w @ g_w
__device__ float g_Wc  [(size_t)RWS * DQ];       // 32 MB  : folded [theta;phi;M]*inv
__device__ float g_bc  [RWS];                    // folded biases
__device__ float g_H   [(size_t)BQ * DTQ];       // 268 MB : running h  [B,D,T]
__device__ float g_C   [(size_t)BQ * CRW];       // 537 MB : projections [B,4096,T]
__device__ float g_F   [(size_t)BQ * DTQ];       // 268 MB : relu(final)
__device__ float g_Y1  [(size_t)BQ * 512];       // fc1 out

// ---------------- small prep kernels ----------------
__global__ void k_bn_prep(const float* __restrict__ gamma, const float* __restrict__ beta,
                          const float* __restrict__ mean,  const float* __restrict__ var) {
    int d = blockIdx.x * blockDim.x + threadIdx.x;
    if (d < DQ) {
        float inv = gamma[d] * rsqrtf(var[d] + 1e-5f);
        float ca  = beta[d] - mean[d] * inv;
        g_inv[d]  = inv;
        g_cadd[d] = ca;
        g_cc[d]   = ca * (2.0f * inv + 1.0f);
    }
}

__global__ void k_fold(const float* __restrict__ thw, const float* __restrict__ phw) {
    int idx = blockIdx.x * blockDim.x + threadIdx.x;   // 4096*2048 total
    int o = idx >> 11;
    int d = idx & 2047;
    float w;
    if (o < 1024)       w = thw[(size_t)o * DQ + d];
    else if (o < 2048)  w = phw[(size_t)(o - 1024) * DQ + d];
    else                w = g_M[(size_t)(o - 2048) * DQ + d];
    g_Wc[idx] = w * g_inv[d];
}

__global__ void k_bias(const float* __restrict__ thw, const float* __restrict__ phw) {
    int o = blockIdx.x;          // 4096 blocks
    int tid = threadIdx.x;       // 256
    const float* row;
    if (o < 1024)      row = thw + (size_t)o * DQ;
    else if (o < 2048) row = phw + (size_t)(o - 1024) * DQ;
    else               row = g_M + (size_t)(o - 2048) * DQ;
    float acc = 0.f;
    for (int d = tid; d < DQ; d += 256) acc += row[d] * g_cadd[d];
    __shared__ float red[256];
    red[tid] = acc;
    __syncthreads();
    for (int st = 128; st > 0; st >>= 1) {
        if (tid < st) red[tid] += red[tid + st];
        __syncthreads();
    }
    if (tid == 0) g_bc[o] = red[0];
}

__global__ void k_copy_x(const float* __restrict__ x) {
    size_t n4 = (size_t)BQ * DTQ / 4;
    for (size_t i = blockIdx.x * (size_t)blockDim.x + threadIdx.x; i < n4;
         i += (size_t)gridDim.x * blockDim.x) {
        ((float4*)g_H)[i] = ((const float4*)x)[i];
    }
}

// ---------------- main GEMM: C[b,o,t] = sum_d Wc[o,d]*H[b,d,t] + bc[o] ----------------
// M=4096 (o), N=32768 (col j=b*16+t), K=2048. Tile 128x128x16, 256 threads, 8x8/thread.
__global__ __launch_bounds__(256) void k_gemm_main() {
    __shared__ float As[16][132];
    __shared__ float Bs[16][132];
    const int tid = threadIdx.x;
    const int rx  = tid & 15;
    const int ry  = tid >> 4;
    const int row0 = blockIdx.y * 128;
    const int col0 = blockIdx.x * 128;
    const int b0   = col0 >> 4;

    float acc[8][8];
#pragma unroll
    for (int i = 0; i < 8; i++)
#pragma unroll
        for (int j = 0; j < 8; j++) acc[i][j] = 0.f;

    for (int k0 = 0; k0 < DQ; k0 += 16) {
#pragma unroll
        for (int f = tid; f < 512; f += 256) {
            int r  = f >> 2;
            int kk = (f & 3) << 2;
            float4 v = *(const float4*)(&g_Wc[(size_t)(row0 + r) * DQ + k0 + kk]);
            As[kk + 0][r] = v.x; As[kk + 1][r] = v.y;
            As[kk + 2][r] = v.z; As[kk + 3][r] = v.w;
        }
#pragma unroll
        for (int f = tid; f < 512; f += 256) {
            int k  = f >> 5;
            int cc = (f & 31) << 2;
            int bb = b0 + (cc >> 4);
            int t  = cc & 15;
            float4 v = *(const float4*)(&g_H[(size_t)bb * DTQ + (k0 + k) * TQ + t]);
            *(float4*)(&Bs[k][cc]) = v;
        }
        __syncthreads();
#pragma unroll
        for (int k = 0; k < 16; k++) {
            float ra[8], rb[8];
            *(float4*)(ra)     = *(const float4*)(&As[k][ry * 4]);
            *(float4*)(ra + 4) = *(const float4*)(&As[k][64 + ry * 4]);
            *(float4*)(rb)     = *(const float4*)(&Bs[k][rx * 4]);
            *(float4*)(rb + 4) = *(const float4*)(&Bs[k][64 + rx * 4]);
#pragma unroll
            for (int i = 0; i < 8; i++)
#pragma unroll
                for (int j = 0; j < 8; j++) acc[i][j] += ra[i] * rb[j];
        }
        __syncthreads();
    }
#pragma unroll
    for (int ih = 0; ih < 2; ih++)
#pragma unroll
        for (int i = 0; i < 4; i++) {
            const int o  = row0 + ih * 64 + ry * 4 + i;
            const float bo = g_bc[o];
#pragma unroll
            for (int jh = 0; jh < 2; jh++) {
                const int c  = jh * 64 + rx * 4;
                const int j  = col0 + c;
                const int bb = j >> 4;
                const int t  = j & 15;
                float4 v;
                v.x = acc[ih * 4 + i][jh * 4 + 0] + bo;
                v.y = acc[ih * 4 + i][jh * 4 + 1] + bo;
                v.z = acc[ih * 4 + i][jh * 4 + 2] + bo;
                v.w = acc[ih * 4 + i][jh * 4 + 3] + bo;
                *(float4*)(&g_C[(size_t)bb * CRW + o * TQ + t]) = v;
            }
        }
}

// ---------------- attention + residual update (per batch item) ----------------
// scores = theta^T phi / DH; alpha = softmax; c1 = G @ alpha^T;
// h_next = inv^2*c1 + (1+inv^2)*h + cc   (in place on g_H)
__global__ __launch_bounds__(256) void k_attn_update() {
    const int b   = blockIdx.x;
    const int tid = threadIdx.x;
    const float* Cb = g_C + (size_t)b * CRW;
    float*       Hb = g_H + (size_t)b * DTQ;

    __shared__ float sth[128 * 16];
    __shared__ float sph[128 * 16];
    __shared__ float sS[16][16];
    __shared__ float sA[16][16];

    const int t = tid >> 4;
    const int s = tid & 15;
    float acc = 0.f;
    for (int o0 = 0; o0 < DHQ; o0 += 128) {
        const float4* srcT = (const float4*)(Cb + o0 * TQ);           // theta rows o0..o0+127
        const float4* srcP = (const float4*)(Cb + DHQ * TQ + o0 * TQ); // phi
        float4* d1 = (float4*)sth;
        float4* d2 = (float4*)sph;
#pragma unroll
        for (int i = tid; i < 512; i += 256) { d1[i] = srcT[i]; d2[i] = srcP[i]; }
        __syncthreads();
#pragma unroll 8
        for (int k = 0; k < 128; k++) acc += sth[k * 16 + t] * sph[k * 16 + s];
        __syncthreads();
    }
    sS[t][s] = acc * (1.0f / (float)DHQ);
    __syncthreads();

    if (tid < 16) {
        float mx = sS[tid][0];
#pragma unroll
        for (int j = 1; j < 16; j++) mx = fmaxf(mx, sS[tid][j]);
        float e[16];
        float sum = 0.f;
#pragma unroll
        for (int j = 0; j < 16; j++) { e[j] = expf(sS[tid][j] - mx); sum += e[j]; }
        float rs = 1.0f / sum;
#pragma unroll
        for (int j = 0; j < 16; j++) sA[tid][j] = e[j] * rs;
    }
    __syncthreads();

    for (int d = tid; d < DQ; d += 256) {
        const float4* gp = (const float4*)(Cb + (size_t)(2048 + d) * TQ);
        float gv[16];
        *(float4*)(gv)      = gp[0];
        *(float4*)(gv + 4)  = gp[1];
        *(float4*)(gv + 8)  = gp[2];
        *(float4*)(gv + 12) = gp[3];
        float4* hp = (float4*)(Hb + (size_t)d * TQ);
        float hv[16];
        *(float4*)(hv)      = hp[0];
        *(float4*)(hv + 4)  = hp[1];
        *(float4*)(hv + 8)  = hp[2];
        *(float4*)(hv + 12) = hp[3];
        const float inv = g_inv[d];
        const float i2  = inv * inv;
        const float a1  = 1.0f + i2;
        const float ccv = g_cc[d];
        float ov[16];
#pragma unroll
        for (int tt = 0; tt < 16; tt++) {
            float c1 = 0.f;
#pragma unroll
            for (int ss = 0; ss < 16; ss++) c1 += sA[tt][ss] * gv[ss];
            ov[tt] = i2 * c1 + a1 * hv[tt] + ccv;
        }
        hp[0] = *(float4*)(ov);
        hp[1] = *(float4*)(ov + 4);
        hp[2] = *(float4*)(ov + 8);
        hp[3] = *(float4*)(ov + 12);
    }
}

// ---------------- M = W_w @ g_w  (2048 x 2048, K=1024) ----------------
__global__ __launch_bounds__(256) void k_gemm_M(const float* __restrict__ A,
                                                const float* __restrict__ B) {
    __shared__ float As[16][132];
    __shared__ float Bs[16][132];
    const int tid = threadIdx.x;
    const int rx  = tid & 15;
    const int ry  = tid >> 4;
    const int row0 = blockIdx.y * 128;
    const int col0 = blockIdx.x * 128;

    float acc[8][8];
#pragma unroll
    for (int i = 0; i < 8; i++)
#pragma unroll
        for (int j = 0; j < 8; j++) acc[i][j] = 0.f;

    for (int k0 = 0; k0 < DHQ; k0 += 16) {
#pragma unroll
        for (int f = tid; f < 512; f += 256) {
            int r  = f >> 2;
            int kk = (f & 3) << 2;
            float4 v = *(const float4*)(&A[(size_t)(row0 + r) * DHQ + k0 + kk]);
            As[kk + 0][r] = v.x; As[kk + 1][r] = v.y;
            As[kk + 2][r] = v.z; As[kk + 3][r] = v.w;
        }
#pragma unroll
        for (int f = tid; f < 512; f += 256) {
            int k  = f >> 5;
            int cc = (f & 31) << 2;
            float4 v = *(const float4*)(&B[(size_t)(k0 + k) * DQ + col0 + cc]);
            *(float4*)(&Bs[k][cc]) = v;
        }
        __syncthreads();
#pragma unroll
        for (int k = 0; k < 16; k++) {
            float ra[8], rb[8];
            *(float4*)(ra)     = *(const float4*)(&As[k][ry * 4]);
            *(float4*)(ra + 4) = *(const float4*)(&As[k][64 + ry * 4]);
            *(float4*)(rb)     = *(const float4*)(&Bs[k][rx * 4]);
            *(float4*)(rb + 4) = *(const float4*)(&Bs[k][64 + rx * 4]);
#pragma unroll
            for (int i = 0; i < 8; i++)
#pragma unroll
                for (int j = 0; j < 8; j++) acc[i][j] += ra[i] * rb[j];
        }
        __syncthreads();
    }
#pragma unroll
    for (int ih = 0; ih < 2; ih++)
#pragma unroll
        for (int i = 0; i < 4; i++) {
            const int r = row0 + ih * 64 + ry * 4 + i;
#pragma unroll
            for (int jh = 0; jh < 2; jh++) {
                const int c = col0 + jh * 64 + rx * 4;
                float4 v;
                v.x = acc[ih * 4 + i][jh * 4 + 0];
                v.y = acc[ih * 4 + i][jh * 4 + 1];
                v.z = acc[ih * 4 + i][jh * 4 + 2];
                v.w = acc[ih * 4 + i][jh * 4 + 3];
                *(float4*)(&g_M[(size_t)r * DQ + c]) = v;
            }
        }
}

// ---------------- final: F = relu(BN(h) + x) over flat [B, 32768] ----------------
__global__ void k_final(const float* __restrict__ x) {
    size_t n4 = (size_t)BQ * DTQ / 4;
    for (size_t i4 = blockIdx.x * (size_t)blockDim.x + threadIdx.x; i4 < n4;
         i4 += (size_t)gridDim.x * blockDim.x) {
        size_t i = i4 * 4;
        int j = (int)(i & (DTQ - 1));
        int d = j >> 4;
        float inv = g_inv[d];
        float ca  = g_cadd[d];
        float4 h  = *(const float4*)(&g_H[i]);
        float4 xv = *(const float4*)(&x[i]);
        float4 v;
        v.x = fmaxf(inv * h.x + ca + xv.x, 0.f);
        v.y = fmaxf(inv * h.y + ca + xv.y, 0.f);
        v.z = fmaxf(inv * h.z + ca + xv.z, 0.f);
        v.w = fmaxf(inv * h.w + ca + xv.w, 0.f);
        *(float4*)(&g_F[i]) = v;
    }
}

// ---------------- fc1: Y1 = relu(F @ fc1_w^T + b1)  (NT GEMM, M=2048,N=512,K=32768) ----------------
__global__ __launch_bounds__(256) void k_gemm_fc1(const float* __restrict__ Bw,
                                                  const float* __restrict__ bias) {
    __shared__ float As[16][132];
    __shared__ float Bs[16][132];
    const int tid = threadIdx.x;
    const int rx  = tid & 15;
    const int ry  = tid >> 4;
    const int row0 = blockIdx.y * 128;   // batch rows
    const int col0 = blockIdx.x * 128;   // fc1 output cols

    float acc[8][8];
#pragma unroll
    for (int i = 0; i < 8; i++)
#pragma unroll
        for (int j = 0; j < 8; j++) acc[i][j] = 0.f;

    for (int k0 = 0; k0 < DTQ; k0 += 16) {
#pragma unroll
        for (int f = tid; f < 512; f += 256) {
            int r  = f >> 2;
            int kk = (f & 3) << 2;
            float4 v = *(const float4*)(&g_F[(size_t)(row0 + r) * DTQ + k0 + kk]);
            As[kk + 0][r] = v.x; As[kk + 1][r] = v.y;
            As[kk + 2][r] = v.z; As[kk + 3][r] = v.w;
        }
#pragma unroll
        for (int f = tid; f < 512; f += 256) {
            int cN = f >> 2;
            int kk = (f & 3) << 2;
            float4 v = *(const float4*)(&Bw[(size_t)(col0 + cN) * DTQ + k0 + kk]);
            Bs[kk + 0][cN] = v.x; Bs[kk + 1][cN] = v.y;
            Bs[kk + 2][cN] = v.z; Bs[kk + 3][cN] = v.w;
        }
        __syncthreads();
#pragma unroll
        for (int k = 0; k < 16; k++) {
            float ra[8], rb[8];
            *(float4*)(ra)     = *(const float4*)(&As[k][ry * 4]);
            *(float4*)(ra + 4) = *(const float4*)(&As[k][64 + ry * 4]);
            *(float4*)(rb)     = *(const float4*)(&Bs[k][rx * 4]);
            *(float4*)(rb + 4) = *(const float4*)(&Bs[k][64 + rx * 4]);
#pragma unroll
            for (int i = 0; i < 8; i++)
#pragma unroll
                for (int j = 0; j < 8; j++) acc[i][j] += ra[i] * rb[j];
        }
        __syncthreads();
    }
#pragma unroll
    for (int ih = 0; ih < 2; ih++)
#pragma unroll
        for (int i = 0; i < 4; i++) {
            const int r = row0 + ih * 64 + ry * 4 + i;
#pragma unroll
            for (int jh = 0; jh < 2; jh++) {
                const int c = col0 + jh * 64 + rx * 4;
                float4 v;
                v.x = fmaxf(acc[ih * 4 + i][jh * 4 + 0] + bias[c + 0], 0.f);
                v.y = fmaxf(acc[ih * 4 + i][jh * 4 + 1] + bias[c + 1], 0.f);
                v.z = fmaxf(acc[ih * 4 + i][jh * 4 + 2] + bias[c + 2], 0.f);
                v.w = fmaxf(acc[ih * 4 + i][jh * 4 + 3] + bias[c + 3], 0.f);
                *(float4*)(&g_Y1[(size_t)r * 512 + c]) = v;
            }
        }
}

// ---------------- fc2: out = Y1 @ fc2_w^T + b2 ----------------
__global__ void k_fc2(const float* __restrict__ w, const float* __restrict__ bias,
                      float* __restrict__ out) {
    const int b = blockIdx.x;
    __shared__ float sy[512];
    for (int i = threadIdx.x; i < 512; i += blockDim.x) sy[i] = g_Y1[(size_t)b * 512 + i];
    __syncthreads();
    for (int c = threadIdx.x; c < NCQ; c += blockDim.x) {
        float acc = bias[c];
        const float* wr = w + (size_t)c * 512;
#pragma unroll 8
        for (int n = 0; n < 512; n++) acc += sy[n] * wr[n];
        out[(size_t)b * NCQ + c] = acc;
    }
}

// ---------------- launch ----------------
extern "C" void kernel_launch(void* const* d_in, const int* in_sizes, int n_in,
                              void* d_out, int out_size) {
    const float* x     = (const float*)d_in[0];
    const float* thw   = (const float*)d_in[1];
    const float* phw   = (const float*)d_in[2];
    const float* gw    = (const float*)d_in[3];
    const float* Ww    = (const float*)d_in[4];
    const float* gamma = (const float*)d_in[5];
    const float* beta  = (const float*)d_in[6];
    const float* mean  = (const float*)d_in[7];
    const float* var   = (const float*)d_in[8];
    const float* fc1w  = (const float*)d_in[9];
    const float* fc1b  = (const float*)d_in[10];
    const float* fc2w  = (const float*)d_in[11];
    const float* fc2b  = (const float*)d_in[12];
    float* out = (float*)d_out;

    k_bn_prep<<<(DQ + 255) / 256, 256>>>(gamma, beta, mean, var);
    k_gemm_M<<<dim3(DQ / 128, DQ / 128), 256>>>(Ww, gw);
    k_fold<<<(RWS * DQ) / 256, 256>>>(thw, phw);
    k_bias<<<RWS, 256>>>(thw, phw);
    k_copy_x<<<8192, 256>>>(x);

    for (int it = 0; it < TQ; ++it) {
        k_gemm_main<<<dim3(DTQ / 128, RWS / 128), 256>>>();
        k_attn_update<<<BQ, 256>>>();
    }

    k_final<<<8192, 256>>>(x);
    k_gemm_fc1<<<dim3(512 / 128, BQ / 128), 256>>>(fc1w, fc1b);
    k_fc2<<<BQ, 256>>>(fc2w, fc2b, out);
}

// round 4
// speedup vs baseline: 1.0284x; 1.0284x over previous
#include <cuda_runtime.h>
#include <math.h>
#include <stdint.h>

// Problem constants
#define BQ   2048
#define TQ   16
#define DQ   2048
#define DHQ  1024
#define NCQ  174
#define DTQ  32768          // D*T
#define RWS  4096           // 2*DH + D  (theta; phi; M rows)
#define NTOT 32768          // B*T columns

// GEMM tiling (mma.sync path)
#define MT     128
#define NT     128
#define KC     32
#define NCH    (DQ / KC)    // 64
#define STAGES 3
#define TILEB  (MT * KC * 4)        // 16384 bytes per tile
#define STB    (4 * TILEB)          // Ah, Al, Bh, Bl per stage = 64KB
#define SMEMT  (STAGES * STB)       // 192KB

// ---------------- device scratch ----------------
__device__ float g_inv [DQ];
__device__ float g_cadd[DQ];
__device__ float g_cc  [DQ];
__device__ float g_M     [(size_t)DQ * DQ];       // W_w @ g_w
__device__ float g_Wc_hi [(size_t)RWS * DQ];      // folded weights tf32-hi
__device__ float g_Wc_lo [(size_t)RWS * DQ];      // folded weights tf32-lo
__device__ float g_bc  [RWS];
__device__ float g_Ht_hi [(size_t)NTOT * DQ];     // h, [n=b*16+t][k=d], tf32-hi
__device__ float g_Ht_lo [(size_t)NTOT * DQ];     // tf32-lo
__device__ float g_C     [(size_t)RWS * NTOT];    // projections [o][n]
__device__ float g_F     [(size_t)BQ * DTQ];
__device__ float g_Y1  [(size_t)BQ * 512];

// ---------------- helpers ----------------
__device__ __forceinline__ uint32_t smem_u32(const void* p) {
    uint32_t a;
    asm("{ .reg .u64 t; cvta.to.shared.u64 t, %1; cvt.u32.u64 %0, t; }" : "=r"(a) : "l"(p));
    return a;
}

__device__ __forceinline__ void cp16(uint32_t dst, const void* src) {
    asm volatile("cp.async.cg.shared.global [%0], [%1], 16;" :: "r"(dst), "l"(src));
}
#define CP_COMMIT() asm volatile("cp.async.commit_group;" ::: "memory")
#define CP_WAIT2()  asm volatile("cp.async.wait_group 2;" ::: "memory")

__device__ __forceinline__ void ldm_x4(uint32_t* r, uint32_t addr) {
    asm volatile("ldmatrix.sync.aligned.m8n8.x4.shared.b16 {%0,%1,%2,%3}, [%4];"
                 : "=r"(r[0]), "=r"(r[1]), "=r"(r[2]), "=r"(r[3]) : "r"(addr));
}

__device__ __forceinline__ void mma8(float* c, const uint32_t* a, uint32_t b0, uint32_t b1) {
    asm volatile("mma.sync.aligned.m16n8k8.row.col.f32.tf32.tf32.f32 "
                 "{%0,%1,%2,%3},{%4,%5,%6,%7},{%8,%9},{%0,%1,%2,%3};"
                 : "+f"(c[0]), "+f"(c[1]), "+f"(c[2]), "+f"(c[3])
                 : "r"(a[0]), "r"(a[1]), "r"(a[2]), "r"(a[3]), "r"(b0), "r"(b1));
}

__device__ __forceinline__ void tf32_split(float v, float& hi, float& lo) {
    uint32_t u;
    asm("cvt.rna.tf32.f32 %0, %1;" : "=r"(u) : "f"(v));
    hi = __uint_as_float(u);
    float r = v - hi;
    uint32_t u2;
    asm("cvt.rna.tf32.f32 %0, %1;" : "=r"(u2) : "f"(r));
    lo = __uint_as_float(u2);
}

// swizzled smem byte offset: row (0..127) * 128B + granule^ (row&7)
__device__ __forceinline__ uint32_t sw(int row, int g) {
    return (uint32_t)(row * 128 + ((g ^ (row & 7)) << 4));
}

// ---------------- prep kernels ----------------
__global__ void k_bn_prep(const float* __restrict__ gamma, const float* __restrict__ beta,
                          const float* __restrict__ mean,  const float* __restrict__ var) {
    int d = blockIdx.x * blockDim.x + threadIdx.x;
    if (d < DQ) {
        float inv = gamma[d] * rsqrtf(var[d] + 1e-5f);
        float ca  = beta[d] - mean[d] * inv;
        g_inv[d]  = inv;
        g_cadd[d] = ca;
        g_cc[d]   = ca * (2.0f * inv + 1.0f);
    }
}

__global__ void k_fold(const float* __restrict__ thw, const float* __restrict__ phw) {
    int idx = blockIdx.x * blockDim.x + threadIdx.x;
    int o = idx >> 11;
    int d = idx & 2047;
    float w;
    if (o < 1024)       w = thw[(size_t)o * DQ + d];
    else if (o < 2048)  w = phw[(size_t)(o - 1024) * DQ + d];
    else                w = g_M[(size_t)(o - 2048) * DQ + d];
    float v = w * g_inv[d];
    float hi, lo;
    tf32_split(v, hi, lo);
    g_Wc_hi[idx] = hi;
    g_Wc_lo[idx] = lo;
}

__global__ void k_bias(const float* __restrict__ thw, const float* __restrict__ phw) {
    int o = blockIdx.x;
    int tid = threadIdx.x;
    const float* row;
    if (o < 1024)      row = thw + (size_t)o * DQ;
    else if (o < 2048) row = phw + (size_t)(o - 1024) * DQ;
    else               row = g_M + (size_t)(o - 2048) * DQ;
    float acc = 0.f;
    for (int d = tid; d < DQ; d += 256) acc += row[d] * g_cadd[d];
    __shared__ float red[256];
    red[tid] = acc;
    __syncthreads();
    for (int st = 128; st > 0; st >>= 1) {
        if (tid < st) red[tid] += red[tid + st];
        __syncthreads();
    }
    if (tid == 0) g_bc[o] = red[0];
}

// Ht[n=b*16+t][k=d] = x[b*32768 + d*16 + t] split into tf32 hi/lo
__global__ __launch_bounds__(256) void k_init(const float* __restrict__ x) {
    __shared__ float s[128 * 17];
    int b = blockIdx.x, tid = threadIdx.x;
    for (int d0 = 0; d0 < DQ; d0 += 128) {
        for (int i = tid; i < 2048; i += 256) {
            int dd = i >> 4, t = i & 15;
            s[dd * 17 + t] = x[(size_t)b * DTQ + d0 * 16 + i];
        }
        __syncthreads();
        int t = tid >> 4, j = tid & 15;
        size_t base = ((size_t)(b * 16 + t)) * DQ + d0 + j * 8;
#pragma unroll
        for (int i = 0; i < 8; i++) {
            float v = s[(j * 8 + i) * 17 + t];
            float hi, lo;
            tf32_split(v, hi, lo);
            g_Ht_hi[base + i] = hi;
            g_Ht_lo[base + i] = lo;
        }
        __syncthreads();
    }
}

// ---------------- M = W_w @ g_w (fp32 SIMT, run once) ----------------
__global__ __launch_bounds__(256) void k_gemm_M(const float* __restrict__ A,
                                                const float* __restrict__ B) {
    __shared__ float As[16][132];
    __shared__ float Bs[16][132];
    const int tid = threadIdx.x;
    const int rx  = tid & 15;
    const int ry  = tid >> 4;
    const int row0 = blockIdx.y * 128;
    const int col0 = blockIdx.x * 128;
    float acc[8][8];
#pragma unroll
    for (int i = 0; i < 8; i++)
#pragma unroll
        for (int j = 0; j < 8; j++) acc[i][j] = 0.f;
    for (int k0 = 0; k0 < DHQ; k0 += 16) {
#pragma unroll
        for (int f = tid; f < 512; f += 256) {
            int r = f >> 2, kk = (f & 3) << 2;
            float4 v = *(const float4*)(&A[(size_t)(row0 + r) * DHQ + k0 + kk]);
            As[kk + 0][r] = v.x; As[kk + 1][r] = v.y;
            As[kk + 2][r] = v.z; As[kk + 3][r] = v.w;
        }
#pragma unroll
        for (int f = tid; f < 512; f += 256) {
            int k = f >> 5, cc = (f & 31) << 2;
            float4 v = *(const float4*)(&B[(size_t)(k0 + k) * DQ + col0 + cc]);
            *(float4*)(&Bs[k][cc]) = v;
        }
        __syncthreads();
#pragma unroll
        for (int k = 0; k < 16; k++) {
            float ra[8], rb[8];
            *(float4*)(ra)     = *(const float4*)(&As[k][ry * 4]);
            *(float4*)(ra + 4) = *(const float4*)(&As[k][64 + ry * 4]);
            *(float4*)(rb)     = *(const float4*)(&Bs[k][rx * 4]);
            *(float4*)(rb + 4) = *(const float4*)(&Bs[k][64 + rx * 4]);
#pragma unroll
            for (int i = 0; i < 8; i++)
#pragma unroll
                for (int j = 0; j < 8; j++) acc[i][j] += ra[i] * rb[j];
        }
        __syncthreads();
    }
#pragma unroll
    for (int ih = 0; ih < 2; ih++)
#pragma unroll
        for (int i = 0; i < 4; i++) {
            const int r = row0 + ih * 64 + ry * 4 + i;
#pragma unroll
            for (int jh = 0; jh < 2; jh++) {
                const int c = col0 + jh * 64 + rx * 4;
                float4 v;
                v.x = acc[ih * 4 + i][jh * 4 + 0];
                v.y = acc[ih * 4 + i][jh * 4 + 1];
                v.z = acc[ih * 4 + i][jh * 4 + 2];
                v.w = acc[ih * 4 + i][jh * 4 + 3];
                *(float4*)(&g_M[(size_t)r * DQ + c]) = v;
            }
        }
}

// ---------------- 3xTF32 mma.sync GEMM: C[o][n] = sum_k Wc[o][k]*Ht[n][k] + bc[o] ----------------
// Block 128x128, 8 warps (warp tile 32x64), 3-stage cp.async pipeline.
__global__ __launch_bounds__(256, 1) void k_gemm_mma() {
    extern __shared__ __align__(128) char smem[];
    const uint32_t sb = smem_u32(smem);
    const int tid  = threadIdx.x;
    const int wid  = tid >> 5;
    const int lane = tid & 31;
    const int m0 = blockIdx.x * MT;
    const int n0 = blockIdx.y * NT;
    const int warp_m = (wid & 3) * 32;
    const int warp_n = (wid >> 2) * 64;

    // cp.async fill coordinates: thread t covers row=t>>1, granules (t&1)*4 .. +3
    const int frow = tid >> 1;
    const int fg0  = (tid & 1) * 4;

    float acc[2][8][4];
#pragma unroll
    for (int i = 0; i < 2; i++)
#pragma unroll
        for (int j = 0; j < 8; j++)
#pragma unroll
            for (int k = 0; k < 4; k++) acc[i][j][k] = 0.f;

    // issue one stage of loads (4 tiles: Ah, Al, Bh, Bl)
    auto issue = [&](int c, int st) {
        const uint32_t base = sb + st * STB;
        const int k0 = c * KC;
        const size_t arow = (size_t)(m0 + frow) * DQ + k0;
        const size_t brow = (size_t)(n0 + frow) * DQ + k0;
#pragma unroll
        for (int i = 0; i < 4; i++) {
            const int g = fg0 + i;
            const uint32_t so = sw(frow, g);
            cp16(base + so,             g_Wc_hi + arow + g * 4);
            cp16(base + TILEB + so,     g_Wc_lo + arow + g * 4);
            cp16(base + 2 * TILEB + so, g_Ht_hi + brow + g * 4);
            cp16(base + 3 * TILEB + so, g_Ht_lo + brow + g * 4);
        }
    };

    issue(0, 0); CP_COMMIT();
    issue(1, 1); CP_COMMIT();

    // ldmatrix lane addressing precompute
    const int lt   = lane >> 3;        // tile index 0..3
    const int lr   = lane & 7;
    // A: tile t -> rows (t&1)*8 + lr within m16, granule offset (t>>1)
    const int a_rin = lr + ((lt & 1) << 3);
    const int a_gof = lt >> 1;
    // B: tile t -> n8 sub (t>>1), granule offset (t&1)
    const int b_nof = (lt >> 1) * 8 + lr;
    const int b_gof = lt & 1;

    for (int c = 0; c < NCH; c++) {
        const int st_next = (c + 2) % STAGES;
        if (c + 2 < NCH) issue(c + 2, st_next);
        CP_COMMIT();
        CP_WAIT2();
        __syncthreads();

        const uint32_t base  = sb + (c % STAGES) * STB;
        const uint32_t aHi = base;
        const uint32_t aLo = base + TILEB;
        const uint32_t bHi = base + 2 * TILEB;
        const uint32_t bLo = base + 3 * TILEB;

#pragma unroll
        for (int kk = 0; kk < 4; kk++) {
            uint32_t ah[2][4], al[2][4], bh[4][4], bl[4][4];
#pragma unroll
            for (int mt = 0; mt < 2; mt++) {
                const int R = warp_m + mt * 16 + a_rin;
                const uint32_t off = sw(R, kk * 2 + a_gof);
                ldm_x4(ah[mt], aHi + off);
                ldm_x4(al[mt], aLo + off);
            }
#pragma unroll
            for (int p = 0; p < 4; p++) {
                const int R = warp_n + p * 16 + b_nof;
                const uint32_t off = sw(R, kk * 2 + b_gof);
                ldm_x4(bh[p], bHi + off);
                ldm_x4(bl[p], bLo + off);
            }
#pragma unroll
            for (int mt = 0; mt < 2; mt++)
#pragma unroll
                for (int nt = 0; nt < 8; nt++) {
                    const int p = nt >> 1;
                    const int q = (nt & 1) * 2;
                    mma8(acc[mt][nt], ah[mt], bh[p][q], bh[p][q + 1]);
                    mma8(acc[mt][nt], ah[mt], bl[p][q], bl[p][q + 1]);
                    mma8(acc[mt][nt], al[mt], bh[p][q], bh[p][q + 1]);
                }
        }
        __syncthreads();
    }

    // epilogue: write C with bias
#pragma unroll
    for (int mt = 0; mt < 2; mt++) {
        const int R0 = m0 + warp_m + mt * 16 + (lane >> 2);
        const float b0v = g_bc[R0];
        const float b1v = g_bc[R0 + 8];
#pragma unroll
        for (int nt = 0; nt < 8; nt++) {
            const int col = n0 + warp_n + nt * 8 + 2 * (lane & 3);
            float2 v0 = make_float2(acc[mt][nt][0] + b0v, acc[mt][nt][1] + b0v);
            float2 v1 = make_float2(acc[mt][nt][2] + b1v, acc[mt][nt][3] + b1v);
            *(float2*)(&g_C[(size_t)R0 * NTOT + col])       = v0;
            *(float2*)(&g_C[(size_t)(R0 + 8) * NTOT + col]) = v1;
        }
    }
}

// ---------------- attention + residual update (per batch item) ----------------
__global__ __launch_bounds__(256) void k_attn_update() {
    const int b = blockIdx.x;
    const int tid = threadIdx.x;
    const size_t cb = (size_t)b * 16;

    __shared__ float sth[128 * 16];
    __shared__ float sph[128 * 16];
    __shared__ float sS[16][16];
    __shared__ float sA[16][16];
    __shared__ float sg[64][17];

    const int t16 = tid >> 4;
    const int s16 = tid & 15;

    float acc = 0.f;
    const int r4 = tid >> 2, p4 = tid & 3;
    for (int o0 = 0; o0 < DHQ; o0 += 128) {
#pragma unroll
        for (int pass = 0; pass < 2; pass++) {
            int rr = r4 + pass * 64;
            float4 v1 = *(const float4*)(&g_C[(size_t)(o0 + rr) * NTOT + cb + p4 * 4]);
            *(float4*)(&sth[rr * 16 + p4 * 4]) = v1;
            float4 v2 = *(const float4*)(&g_C[(size_t)(DHQ + o0 + rr) * NTOT + cb + p4 * 4]);
            *(float4*)(&sph[rr * 16 + p4 * 4]) = v2;
        }
        __syncthreads();
#pragma unroll 8
        for (int k = 0; k < 128; k++) acc += sth[k * 16 + t16] * sph[k * 16 + s16];
        __syncthreads();
    }
    sS[t16][s16] = acc * (1.0f / (float)DHQ);
    __syncthreads();

    if (tid < 16) {
        float mx = sS[tid][0];
#pragma unroll
        for (int j = 1; j < 16; j++) mx = fmaxf(mx, sS[tid][j]);
        float e[16], sum = 0.f;
#pragma unroll
        for (int j = 0; j < 16; j++) { e[j] = expf(sS[tid][j] - mx); sum += e[j]; }
        float rs = 1.0f / sum;
#pragma unroll
        for (int j = 0; j < 16; j++) sA[tid][j] = e[j] * rs;
    }
    __syncthreads();

    const int tt = tid >> 4;
    const int jj = tid & 15;
    for (int d0 = 0; d0 < DQ; d0 += 64) {
        {
            float4 gv = *(const float4*)(&g_C[(size_t)(2048 + d0 + r4) * NTOT + cb + p4 * 4]);
            sg[r4][p4 * 4 + 0] = gv.x;
            sg[r4][p4 * 4 + 1] = gv.y;
            sg[r4][p4 * 4 + 2] = gv.z;
            sg[r4][p4 * 4 + 3] = gv.w;
        }
        __syncthreads();

        size_t hidx = ((size_t)(b * 16 + tt)) * DQ + d0 + jj * 4;
        float4 hh = *(const float4*)(&g_Ht_hi[hidx]);
        float4 hl = *(const float4*)(&g_Ht_lo[hidx]);
        float h[4] = {hh.x + hl.x, hh.y + hl.y, hh.z + hl.z, hh.w + hl.w};
        float oh[4], ol[4];
#pragma unroll
        for (int i = 0; i < 4; i++) {
            const int d = d0 + jj * 4 + i;
            float c1 = 0.f;
#pragma unroll
            for (int s = 0; s < 16; s++) c1 += sA[tt][s] * sg[jj * 4 + i][s];
            const float inv = g_inv[d];
            const float i2 = inv * inv;
            const float v = i2 * c1 + (1.0f + i2) * h[i] + g_cc[d];
            tf32_split(v, oh[i], ol[i]);
        }
        *(float4*)(&g_Ht_hi[hidx]) = *(float4*)oh;
        *(float4*)(&g_Ht_lo[hidx]) = *(float4*)ol;
        __syncthreads();
    }
}

// ---------------- final: F[b*32768 + t*2048 + d] = relu(BN(h)+x) with layout transpose ----------
// h lives in Ht[(b,tt)][dch]. Output flat f = b*32768 + q*2048 + (u*16 + tt)
// maps to channel dch = q*128 + u, row tt. One block per (b, q).
__global__ __launch_bounds__(256) void k_final(const float* __restrict__ x) {
    __shared__ float s[16][132];
    const int b = blockIdx.x >> 4;
    const int q = blockIdx.x & 15;
    const int tid = threadIdx.x;

    // load 16 (tt) x 128 (u) tile, apply BN at load
    const int tt = tid >> 4;            // 0..15
    const int ug = (tid & 15);          // 0..15, each covers 2 float4 = 8 u
    const size_t base = ((size_t)(b * 16 + tt)) * DQ + q * 128;
#pragma unroll
    for (int r = 0; r < 2; r++) {
        const int uu = ug * 8 + r * 4;
        float4 hh = *(const float4*)(&g_Ht_hi[base + uu]);
        float4 hl = *(const float4*)(&g_Ht_lo[base + uu]);
        float4 inv4 = *(const float4*)(&g_inv[q * 128 + uu]);
        float4 ca4  = *(const float4*)(&g_cadd[q * 128 + uu]);
        s[tt][uu + 0] = inv4.x * (hh.x + hl.x) + ca4.x;
        s[tt][uu + 1] = inv4.y * (hh.y + hl.y) + ca4.y;
        s[tt][uu + 2] = inv4.z * (hh.z + hl.z) + ca4.z;
        s[tt][uu + 3] = inv4.w * (hh.w + hl.w) + ca4.w;
    }
    __syncthreads();

    // write contiguous output region: o = u*16 + tt, o in [0,2048)
    const size_t f0 = (size_t)b * DTQ + q * 2048;
    const int o0 = tid * 8;
    float4 xa = *(const float4*)(&x[f0 + o0]);
    float4 xb = *(const float4*)(&x[f0 + o0 + 4]);
    float vo[8];
#pragma unroll
    for (int r = 0; r < 8; r++) {
        const int o = o0 + r;
        vo[r] = s[o & 15][o >> 4];
    }
    float4 va, vb;
    va.x = fmaxf(vo[0] + xa.x, 0.f);
    va.y = fmaxf(vo[1] + xa.y, 0.f);
    va.z = fmaxf(vo[2] + xa.z, 0.f);
    va.w = fmaxf(vo[3] + xa.w, 0.f);
    vb.x = fmaxf(vo[4] + xb.x, 0.f);
    vb.y = fmaxf(vo[5] + xb.y, 0.f);
    vb.z = fmaxf(vo[6] + xb.z, 0.f);
    vb.w = fmaxf(vo[7] + xb.w, 0.f);
    *(float4*)(&g_F[f0 + o0])     = va;
    *(float4*)(&g_F[f0 + o0 + 4]) = vb;
}

// ---------------- fc1: Y1 = relu(F @ fc1_w^T + b1) ----------------
__global__ __launch_bounds__(256) void k_gemm_fc1(const float* __restrict__ Bw,
                                                  const float* __restrict__ bias) {
    __shared__ float As[16][132];
    __shared__ float Bs[16][132];
    const int tid = threadIdx.x;
    const int rx  = tid & 15;
    const int ry  = tid >> 4;
    const int row0 = blockIdx.y * 128;
    const int col0 = blockIdx.x * 128;
    float acc[8][8];
#pragma unroll
    for (int i = 0; i < 8; i++)
#pragma unroll
        for (int j = 0; j < 8; j++) acc[i][j] = 0.f;
    for (int k0 = 0; k0 < DTQ; k0 += 16) {
#pragma unroll
        for (int f = tid; f < 512; f += 256) {
            int r = f >> 2, kk = (f & 3) << 2;
            float4 v = *(const float4*)(&g_F[(size_t)(row0 + r) * DTQ + k0 + kk]);
            As[kk + 0][r] = v.x; As[kk + 1][r] = v.y;
            As[kk + 2][r] = v.z; As[kk + 3][r] = v.w;
        }
#pragma unroll
        for (int f = tid; f < 512; f += 256) {
            int cN = f >> 2, kk = (f & 3) << 2;
            float4 v = *(const float4*)(&Bw[(size_t)(col0 + cN) * DTQ + k0 + kk]);
            Bs[kk + 0][cN] = v.x; Bs[kk + 1][cN] = v.y;
            Bs[kk + 2][cN] = v.z; Bs[kk + 3][cN] = v.w;
        }
        __syncthreads();
#pragma unroll
        for (int k = 0; k < 16; k++) {
            float ra[8], rb[8];
            *(float4*)(ra)     = *(const float4*)(&As[k][ry * 4]);
            *(float4*)(ra + 4) = *(const float4*)(&As[k][64 + ry * 4]);
            *(float4*)(rb)     = *(const float4*)(&Bs[k][rx * 4]);
            *(float4*)(rb + 4) = *(const float4*)(&Bs[k][64 + rx * 4]);
#pragma unroll
            for (int i = 0; i < 8; i++)
#pragma unroll
                for (int j = 0; j < 8; j++) acc[i][j] += ra[i] * rb[j];
        }
        __syncthreads();
    }
#pragma unroll
    for (int ih = 0; ih < 2; ih++)
#pragma unroll
        for (int i = 0; i < 4; i++) {
            const int r = row0 + ih * 64 + ry * 4 + i;
#pragma unroll
            for (int jh = 0; jh < 2; jh++) {
                const int c = col0 + jh * 64 + rx * 4;
                float4 v;
                v.x = fmaxf(acc[ih * 4 + i][jh * 4 + 0] + bias[c + 0], 0.f);
                v.y = fmaxf(acc[ih * 4 + i][jh * 4 + 1] + bias[c + 1], 0.f);
                v.z = fmaxf(acc[ih * 4 + i][jh * 4 + 2] + bias[c + 2], 0.f);
                v.w = fmaxf(acc[ih * 4 + i][jh * 4 + 3] + bias[c + 3], 0.f);
                *(float4*)(&g_Y1[(size_t)r * 512 + c]) = v;
            }
        }
}

// ---------------- fc2 ----------------
__global__ void k_fc2(const float* __restrict__ w, const float* __restrict__ bias,
                      float* __restrict__ out) {
    const int b = blockIdx.x;
    __shared__ float sy[512];
    for (int i = threadIdx.x; i < 512; i += blockDim.x) sy[i] = g_Y1[(size_t)b * 512 + i];
    __syncthreads();
    for (int c = threadIdx.x; c < NCQ; c += blockDim.x) {
        float acc = bias[c];
        const float* wr = w + (size_t)c * 512;
#pragma unroll 8
        for (int n = 0; n < 512; n++) acc += sy[n] * wr[n];
        out[(size_t)b * NCQ + c] = acc;
    }
}

// ---------------- launch ----------------
extern "C" void kernel_launch(void* const* d_in, const int* in_sizes, int n_in,
                              void* d_out, int out_size) {
    const float* x     = (const float*)d_in[0];
    const float* thw   = (const float*)d_in[1];
    const float* phw   = (const float*)d_in[2];
    const float* gw    = (const float*)d_in[3];
    const float* Ww    = (const float*)d_in[4];
    const float* gamma = (const float*)d_in[5];
    const float* beta  = (const float*)d_in[6];
    const float* mean  = (const float*)d_in[7];
    const float* var   = (const float*)d_in[8];
    const float* fc1w  = (const float*)d_in[9];
    const float* fc1b  = (const float*)d_in[10];
    const float* fc2w  = (const float*)d_in[11];
    const float* fc2b  = (const float*)d_in[12];
    float* out = (float*)d_out;

    cudaFuncSetAttribute(k_gemm_mma, cudaFuncAttributeMaxDynamicSharedMemorySize, SMEMT);

    k_bn_prep<<<(DQ + 255) / 256, 256>>>(gamma, beta, mean, var);
    k_gemm_M<<<dim3(DQ / 128, DQ / 128), 256>>>(Ww, gw);
    k_fold<<<(RWS * DQ) / 256, 256>>>(thw, phw);
    k_bias<<<RWS, 256>>>(thw, phw);
    k_init<<<BQ, 256>>>(x);

    for (int it = 0; it < TQ; ++it) {
        k_gemm_mma<<<dim3(RWS / MT, NTOT / NT), 256, SMEMT>>>();
        k_attn_update<<<BQ, 256>>>();
    }

    k_final<<<BQ * 16, 256>>>(x);
    k_gemm_fc1<<<dim3(512 / 128, BQ / 128), 256>>>(fc1w, fc1b);
    k_fc2<<<BQ, 256>>>(fc2w, fc2b, out);
}